// round 14
// baseline (speedup 1.0000x reference)
#include <cuda_runtime.h>
#include <cuda_fp16.h>

// ---------------- problem constants ----------------------------------------
#define NMAX   100000
#define EMAX   3200000
#define FEATS  512
#define HIDDEN 64
#define CLASSES 32
#define BUCKET 128            // slots per destination (max deg ~65 for this data)

// ---------------- scratch (static device memory; no allocation) ------------
__device__ int    g_cnt[NMAX];                  // per-dst edge count (cursor)
__device__ int    g_csrs[(size_t)NMAX * BUCKET];// bucketed CSR: src per dst
__device__ float  g_rinv[NMAX];
__device__ float2 g_coef[NMAX];                 // {0.9/deg, sqrt(deg)}
__device__ float4 g_h0u[(size_t)NMAX * 8];      // 0.1 * rinv * h0 (fp32)
__device__ uint4  g_uhA[(size_t)NMAX * 4];      // u as half8 rows (64 B)
__device__ uint4  g_uhB[(size_t)NMAX * 4];

// ---------------- f32x2 packed-FMA helpers (sm_100+) ------------------------
__device__ __forceinline__ unsigned long long pack2(float lo, float hi) {
    unsigned long long r;
    asm("mov.b64 %0, {%1, %2};" : "=l"(r) : "f"(lo), "f"(hi));
    return r;
}
__device__ __forceinline__ void ffma2(unsigned long long& d,
                                      unsigned long long a,
                                      unsigned long long b) {
    asm("fma.rn.f32x2 %0, %1, %2, %0;" : "+l"(d) : "l"(a), "l"(b));
}
__device__ __forceinline__ float2 unpack2(unsigned long long v) {
    float2 f;
    asm("mov.b64 {%0, %1}, %2;" : "=f"(f.x), "=f"(f.y) : "l"(v));
    return f;
}

// half8 helpers
__device__ __forceinline__ void acc8(float4& lo, float4& hi, uint4 v) {
    float2 p;
    p = __half22float2(*(__half2*)&v.x); lo.x += p.x; lo.y += p.y;
    p = __half22float2(*(__half2*)&v.y); lo.z += p.x; lo.w += p.y;
    p = __half22float2(*(__half2*)&v.z); hi.x += p.x; hi.y += p.y;
    p = __half22float2(*(__half2*)&v.w); hi.z += p.x; hi.w += p.y;
}
__device__ __forceinline__ uint4 pack8(float4 lo, float4 hi) {
    uint4 r;
    *(__half2*)&r.x = __floats2half2_rn(lo.x, lo.y);
    *(__half2*)&r.y = __floats2half2_rn(lo.z, lo.w);
    *(__half2*)&r.z = __floats2half2_rn(hi.x, hi.y);
    *(__half2*)&r.w = __floats2half2_rn(hi.z, hi.w);
    return r;
}

// ---------------- setup kernels ---------------------------------------------
__global__ void zero_kernel(int n) {
    int i = blockIdx.x * blockDim.x + threadIdx.x;
    if (i < n) g_cnt[i] = 0;
}

// Single edge pass: build bucketed CSR; count doubles as degree.
__global__ void fill_kernel(const int* __restrict__ edges, int E) {
    int i = blockIdx.x * blockDim.x + threadIdx.x;
    int E4 = E >> 2;
    const int4* src4 = (const int4*)edges;
    const int4* dst4 = (const int4*)(edges + E);
    if (i < E4) {
        int4 s = __ldg(&src4[i]);
        int4 d = __ldg(&dst4[i]);
        int p;
        p = min(atomicAdd(&g_cnt[d.x], 1), BUCKET - 1);
        g_csrs[(size_t)d.x * BUCKET + p] = s.x;
        p = min(atomicAdd(&g_cnt[d.y], 1), BUCKET - 1);
        g_csrs[(size_t)d.y * BUCKET + p] = s.y;
        p = min(atomicAdd(&g_cnt[d.z], 1), BUCKET - 1);
        g_csrs[(size_t)d.z * BUCKET + p] = s.z;
        p = min(atomicAdd(&g_cnt[d.w], 1), BUCKET - 1);
        g_csrs[(size_t)d.w * BUCKET + p] = s.w;
    }
    int tail = E & 3;
    if (i < tail) {
        int s = edges[E4 * 4 + i];
        int d = edges[E + E4 * 4 + i];
        int p = min(atomicAdd(&g_cnt[d], 1), BUCKET - 1);
        g_csrs[(size_t)d * BUCKET + p] = s;
    }
}

__global__ void coef_kernel(int n) {
    int i = blockIdx.x * blockDim.x + threadIdx.x;
    if (i >= n) return;
    float fd = (float)max(g_cnt[i], 1);
    g_rinv[i] = rsqrtf(fd);
    g_coef[i] = make_float2(0.9f / fd, sqrtf(fd));
}

// ---------------- fused MLP: h0 = relu(x@W1+b1)@W2 + b2, write u seeds ------
__global__ __launch_bounds__(256, 2)
void mlp_fused_kernel(const float* __restrict__ x,
                      const float* __restrict__ W1,
                      const float* __restrict__ b1,
                      const float* __restrict__ W2,
                      const float* __restrict__ b2, int n) {
    __shared__ float sh[8192];     // 32 KB: [As 16x256 | Ws 16x64] then Hs 128x64
    __shared__ float W2s[HIDDEN * CLASSES];  // 8 KB
    __shared__ float b2s[CLASSES];
    float* As = sh;                // [k][node] : k*256+node
    float* Ws = sh + 4096;         // [k][hid]  : k*64+hid

    int tid = threadIdx.x;
    int tx  = tid & 7;
    int ty  = tid >> 3;
    int bn  = blockIdx.x * 256;

    for (int i = tid; i < HIDDEN * CLASSES; i += 256) W2s[i] = W2[i];
    if (tid < CLASSES) b2s[tid] = b2[tid];

    int anode = tid >> 2;
    int ak    = (tid & 3) * 4;
    int wk    = tid >> 4;
    int wc    = (tid & 15) * 4;

    unsigned long long acc[8][4];
    #pragma unroll
    for (int i = 0; i < 8; i++)
        #pragma unroll
        for (int j = 0; j < 4; j++) acc[i][j] = 0ULL;

    for (int k0 = 0; k0 < FEATS; k0 += 16) {
        #pragma unroll
        for (int r = 0; r < 4; r++) {
            int nd = anode + r * 64;
            int node = bn + nd;
            float4 av = make_float4(0.f, 0.f, 0.f, 0.f);
            if (node < n)
                av = *(const float4*)&x[(size_t)node * FEATS + k0 + ak];
            As[(ak + 0) * 256 + nd] = av.x;
            As[(ak + 1) * 256 + nd] = av.y;
            As[(ak + 2) * 256 + nd] = av.z;
            As[(ak + 3) * 256 + nd] = av.w;
        }
        *(float4*)&Ws[wk * 64 + wc] = *(const float4*)&W1[(size_t)(k0 + wk) * HIDDEN + wc];
        __syncthreads();
        #pragma unroll
        for (int k = 0; k < 16; k++) {
            float4 a0 = *(const float4*)&As[k * 256 + ty * 8];
            float4 a1 = *(const float4*)&As[k * 256 + ty * 8 + 4];
            ulonglong2 bp01 = *(const ulonglong2*)&Ws[k * 64 + tx * 8];
            ulonglong2 bp23 = *(const ulonglong2*)&Ws[k * 64 + tx * 8 + 4];
            float av[8] = {a0.x, a0.y, a0.z, a0.w, a1.x, a1.y, a1.z, a1.w};
            #pragma unroll
            for (int i = 0; i < 8; i++) {
                unsigned long long ad = pack2(av[i], av[i]);
                ffma2(acc[i][0], ad, bp01.x);
                ffma2(acc[i][1], ad, bp01.y);
                ffma2(acc[i][2], ad, bp23.x);
                ffma2(acc[i][3], ad, bp23.y);
            }
        }
        __syncthreads();
    }

    float4 bb0 = *(const float4*)&b1[tx * 8];
    float4 bb1 = *(const float4*)&b1[tx * 8 + 4];
    int lane = tid & 31;
    int w    = tid >> 5;
    float* h0u = (float*)g_h0u;
    __half* uA = (__half*)g_uhA;

    #pragma unroll 1
    for (int h = 0; h < 2; h++) {
        if ((ty >> 4) == h) {
            int lty = ty & 15;
            #pragma unroll
            for (int i = 0; i < 8; i++) {
                int ln = lty * 8 + i;
                if (bn + h * 128 + ln < n) {
                    float2 p0 = unpack2(acc[i][0]);
                    float2 p1 = unpack2(acc[i][1]);
                    float2 p2 = unpack2(acc[i][2]);
                    float2 p3 = unpack2(acc[i][3]);
                    float* hr = &sh[ln * 64 + tx * 8];
                    hr[0] = fmaxf(p0.x + bb0.x, 0.f);
                    hr[1] = fmaxf(p0.y + bb0.y, 0.f);
                    hr[2] = fmaxf(p1.x + bb0.z, 0.f);
                    hr[3] = fmaxf(p1.y + bb0.w, 0.f);
                    hr[4] = fmaxf(p2.x + bb1.x, 0.f);
                    hr[5] = fmaxf(p2.y + bb1.y, 0.f);
                    hr[6] = fmaxf(p3.x + bb1.z, 0.f);
                    hr[7] = fmaxf(p3.y + bb1.w, 0.f);
                }
            }
        }
        __syncthreads();
        #pragma unroll 1
        for (int t = 0; t < 16; t++) {
            int ln = w * 16 + t;
            int node = bn + h * 128 + ln;
            if (node < n) {
                float s = 0.f;
                #pragma unroll
                for (int k4 = 0; k4 < 16; k4++) {
                    float4 hv = *(const float4*)&sh[ln * 64 + k4 * 4];
                    s = fmaf(hv.x, W2s[(k4 * 4 + 0) * CLASSES + lane], s);
                    s = fmaf(hv.y, W2s[(k4 * 4 + 1) * CLASSES + lane], s);
                    s = fmaf(hv.z, W2s[(k4 * 4 + 2) * CLASSES + lane], s);
                    s = fmaf(hv.w, W2s[(k4 * 4 + 3) * CLASSES + lane], s);
                }
                s += b2s[lane];
                float rv = g_rinv[node];
                h0u[(size_t)node * CLASSES + lane] = 0.1f * rv * s;
                uA[(size_t)node * CLASSES + lane]  = __float2half_rn(rv * s);
            }
        }
        __syncthreads();
    }
}

// ---------------- propagation (u-space, fp16 rows, fp32 accumulate) ---------
// One warp per dst node: 8 edge-groups x 4 lanes; lane owns one uint4 (8 halves).
// Bucket CSR: row gw occupies [gw*BUCKET, gw*BUCKET + cnt[gw]).
__global__ void prop_kernel(int parity, float* __restrict__ ext_out, int n) {
    int gw = (blockIdx.x * blockDim.x + threadIdx.x) >> 5;
    if (gw >= n) return;
    int lane = threadIdx.x & 31;
    int grp  = lane >> 2;          // 0..7 edge slot
    int c    = lane & 3;           // 0..3 half8 column

    const uint4* u_in = parity ? g_uhB : g_uhA;
    int beg = gw * BUCKET;
    int end = beg + __ldg(&g_cnt[gw]);

    float4 lo0 = make_float4(0.f, 0.f, 0.f, 0.f), hi0 = lo0;
    float4 lo1 = lo0, hi1 = lo0;
    int i = beg + grp;
    for (; i + 8 < end; i += 16) {
        int s0 = __ldg(&g_csrs[i]);
        int s1 = __ldg(&g_csrs[i + 8]);
        uint4 v0 = __ldg(&u_in[(size_t)s0 * 4 + c]);
        uint4 v1 = __ldg(&u_in[(size_t)s1 * 4 + c]);
        acc8(lo0, hi0, v0);
        acc8(lo1, hi1, v1);
    }
    if (i < end) {
        int s0 = __ldg(&g_csrs[i]);
        uint4 v0 = __ldg(&u_in[(size_t)s0 * 4 + c]);
        acc8(lo0, hi0, v0);
    }
    lo0.x += lo1.x; lo0.y += lo1.y; lo0.z += lo1.z; lo0.w += lo1.w;
    hi0.x += hi1.x; hi0.y += hi1.y; hi0.z += hi1.z; hi0.w += hi1.w;

    #pragma unroll
    for (int off = 4; off <= 16; off <<= 1) {
        lo0.x += __shfl_xor_sync(0xffffffffu, lo0.x, off);
        lo0.y += __shfl_xor_sync(0xffffffffu, lo0.y, off);
        lo0.z += __shfl_xor_sync(0xffffffffu, lo0.z, off);
        lo0.w += __shfl_xor_sync(0xffffffffu, lo0.w, off);
        hi0.x += __shfl_xor_sync(0xffffffffu, hi0.x, off);
        hi0.y += __shfl_xor_sync(0xffffffffu, hi0.y, off);
        hi0.z += __shfl_xor_sync(0xffffffffu, hi0.z, off);
        hi0.w += __shfl_xor_sync(0xffffffffu, hi0.w, off);
    }
    if (grp == 0) {
        float2 cf = __ldg(&g_coef[gw]);
        float4 z0 = __ldg(&g_h0u[(size_t)gw * 8 + c * 2]);
        float4 z1 = __ldg(&g_h0u[(size_t)gw * 8 + c * 2 + 1]);
        float4 o0, o1;
        o0.x = fmaf(cf.x, lo0.x, z0.x);
        o0.y = fmaf(cf.x, lo0.y, z0.y);
        o0.z = fmaf(cf.x, lo0.z, z0.z);
        o0.w = fmaf(cf.x, lo0.w, z0.w);
        o1.x = fmaf(cf.x, hi0.x, z1.x);
        o1.y = fmaf(cf.x, hi0.y, z1.y);
        o1.z = fmaf(cf.x, hi0.z, z1.z);
        o1.w = fmaf(cf.x, hi0.w, z1.w);
        if (ext_out) {  // final iteration: back to h-space, fp32 out
            o0.x *= cf.y; o0.y *= cf.y; o0.z *= cf.y; o0.w *= cf.y;
            o1.x *= cf.y; o1.y *= cf.y; o1.z *= cf.y; o1.w *= cf.y;
            ((float4*)ext_out)[(size_t)gw * 8 + c * 2]     = o0;
            ((float4*)ext_out)[(size_t)gw * 8 + c * 2 + 1] = o1;
        } else {
            uint4* u_out = parity ? g_uhA : g_uhB;
            u_out[(size_t)gw * 4 + c] = pack8(o0, o1);
        }
    }
}

// ---------------- host driver -----------------------------------------------
extern "C" void kernel_launch(void* const* d_in, const int* in_sizes, int n_in,
                              void* d_out, int out_size) {
    const float* x     = (const float*)d_in[0];
    const int*   edges = (const int*)d_in[1];     // int32 (JAX x64 off)
    const float* W1    = (const float*)d_in[2];
    const float* b1    = (const float*)d_in[3];
    const float* W2    = (const float*)d_in[4];
    const float* b2    = (const float*)d_in[5];

    int n = in_sizes[0] / FEATS;
    int E = in_sizes[1] / 2;

    const int TB = 256;
    int E4 = (E >> 2) ? (E >> 2) : 1;
    zero_kernel<<<(n + TB - 1) / TB, TB>>>(n);
    fill_kernel<<<(E4 + TB - 1) / TB, TB>>>(edges, E);
    coef_kernel<<<(n + TB - 1) / TB, TB>>>(n);

    mlp_fused_kernel<<<(n + 255) / 256, 256>>>(x, W1, b1, W2, b2, n);

    int prop_blocks = (n * 32 + TB - 1) / TB;   // one warp per node
    for (int it = 0; it < 10; it++) {
        prop_kernel<<<prop_blocks, TB>>>(it & 1,
                                         (it == 9) ? (float*)d_out : nullptr,
                                         n);
    }
}

// round 15
// speedup vs baseline: 1.1144x; 1.1144x over previous
#include <cuda_runtime.h>
#include <cuda_fp16.h>

// ---------------- problem constants ----------------------------------------
#define NMAX   100000
#define EMAX   3200000
#define FEATS  512
#define HIDDEN 64
#define CLASSES 32
#define SCAN_CHUNK 1024
#define MAX_CHUNKS ((NMAX + SCAN_CHUNK - 1) / SCAN_CHUNK)

// ---------------- scratch (static device memory; no allocation) ------------
__device__ int    g_deg[NMAX];
__device__ int    g_rowptr[NMAX + 1];     // doubles as fill cursor
__device__ int    g_bsum[MAX_CHUNKS];
__device__ int    g_boff[MAX_CHUNKS];
__device__ int    g_csrs[EMAX];           // src only (u-space: no weights)
__device__ float  g_rinv[NMAX];
__device__ float2 g_coef[NMAX];           // {0.9/deg, sqrt(deg)}
__device__ float4 g_h0u[(size_t)NMAX * 8];      // 0.1 * rinv * h0 (fp32)
__device__ uint4  g_uhA[(size_t)NMAX * 4];      // u as half8 rows (64 B)
__device__ uint4  g_uhB[(size_t)NMAX * 4];

// ---------------- f32x2 packed-FMA helpers (sm_100+) ------------------------
__device__ __forceinline__ void ffma2(unsigned long long& d,
                                      unsigned long long a,
                                      unsigned long long b) {
    asm("fma.rn.f32x2 %0, %1, %2, %0;" : "+l"(d) : "l"(a), "l"(b));
}
__device__ __forceinline__ float2 unpack2(unsigned long long v) {
    float2 f;
    asm("mov.b64 {%0, %1}, %2;" : "=f"(f.x), "=f"(f.y) : "l"(v));
    return f;
}

// half8 helpers
__device__ __forceinline__ void acc8(float4& lo, float4& hi, uint4 v) {
    float2 p;
    p = __half22float2(*(__half2*)&v.x); lo.x += p.x; lo.y += p.y;
    p = __half22float2(*(__half2*)&v.y); lo.z += p.x; lo.w += p.y;
    p = __half22float2(*(__half2*)&v.z); hi.x += p.x; hi.y += p.y;
    p = __half22float2(*(__half2*)&v.w); hi.z += p.x; hi.w += p.y;
}
__device__ __forceinline__ uint4 pack8(float4 lo, float4 hi) {
    uint4 r;
    *(__half2*)&r.x = __floats2half2_rn(lo.x, lo.y);
    *(__half2*)&r.y = __floats2half2_rn(lo.z, lo.w);
    *(__half2*)&r.z = __floats2half2_rn(hi.x, hi.y);
    *(__half2*)&r.w = __floats2half2_rn(hi.z, hi.w);
    return r;
}

// ---------------- setup kernels ---------------------------------------------
__global__ void zero_kernel(int n) {
    int i = blockIdx.x * blockDim.x + threadIdx.x;
    if (i < n) g_deg[i] = 0;
}

// 4 edges per thread (int4)
__global__ void deg_kernel(const int* __restrict__ edges, int E) {
    int i = blockIdx.x * blockDim.x + threadIdx.x;
    int E4 = E >> 2;
    const int4* dst4 = (const int4*)(edges + E);
    if (i < E4) {
        int4 d = __ldg(&dst4[i]);
        atomicAdd(&g_deg[d.x], 1);
        atomicAdd(&g_deg[d.y], 1);
        atomicAdd(&g_deg[d.z], 1);
        atomicAdd(&g_deg[d.w], 1);
    }
    int tail = E & 3;
    if (i < tail) atomicAdd(&g_deg[edges[E + E4 * 4 + i]], 1);
}

// ---- decoupled scan phase 1: per-block exclusive scan + block sum + coef ---
__global__ void scan_block_kernel(int n) {
    __shared__ int wsum[32];
    int tid = threadIdx.x, lane = tid & 31, wid = tid >> 5;
    int i = blockIdx.x * SCAN_CHUNK + tid;
    int v = (i < n) ? g_deg[i] : 0;
    if (i < n) {
        float fd = (float)max(v, 1);
        g_rinv[i] = rsqrtf(fd);
        g_coef[i] = make_float2(0.9f / fd, sqrtf(fd));
    }
    int s = v;
    #pragma unroll
    for (int o = 1; o < 32; o <<= 1) {
        int t = __shfl_up_sync(0xffffffffu, s, o);
        if (lane >= o) s += t;
    }
    if (lane == 31) wsum[wid] = s;
    __syncthreads();
    if (wid == 0) {
        int ws = wsum[lane];
        #pragma unroll
        for (int o = 1; o < 32; o <<= 1) {
            int t = __shfl_up_sync(0xffffffffu, ws, o);
            if (lane >= o) ws += t;
        }
        wsum[lane] = ws;
    }
    __syncthreads();
    int incl = s + (wid ? wsum[wid - 1] : 0);
    if (i < n) g_rowptr[i] = incl - v;
    if (tid == SCAN_CHUNK - 1) g_bsum[blockIdx.x] = incl;
}

// phase 2: ONE WARP shuffle-scan of <=98 block sums
__global__ void scan_sums_kernel(int nb, int n) {
    int lane = threadIdx.x;
    int carry = 0;
    for (int base = 0; base < nb; base += 32) {
        int v = (base + lane < nb) ? g_bsum[base + lane] : 0;
        int s = v;
        #pragma unroll
        for (int o = 1; o < 32; o <<= 1) {
            int t = __shfl_up_sync(0xffffffffu, s, o);
            if (lane >= o) s += t;
        }
        if (base + lane < nb) g_boff[base + lane] = carry + s - v;
        carry += __shfl_sync(0xffffffffu, s, 31);
    }
    if (lane == 0) g_rowptr[n] = carry;
}

__global__ void scan_add_kernel(int n) {
    int i = blockIdx.x * blockDim.x + threadIdx.x;
    if (i < n) g_rowptr[i] += g_boff[i >> 10];
}

// 4 edges per thread (int4); rowptr doubles as cursor
__global__ void fill_kernel(const int* __restrict__ edges, int E) {
    int i = blockIdx.x * blockDim.x + threadIdx.x;
    int E4 = E >> 2;
    const int4* src4 = (const int4*)edges;
    const int4* dst4 = (const int4*)(edges + E);
    if (i < E4) {
        int4 s = __ldg(&src4[i]);
        int4 d = __ldg(&dst4[i]);
        g_csrs[atomicAdd(&g_rowptr[d.x], 1)] = s.x;
        g_csrs[atomicAdd(&g_rowptr[d.y], 1)] = s.y;
        g_csrs[atomicAdd(&g_rowptr[d.z], 1)] = s.z;
        g_csrs[atomicAdd(&g_rowptr[d.w], 1)] = s.w;
    }
    int tail = E & 3;
    if (i < tail) {
        int s = edges[E4 * 4 + i];
        int d = edges[E + E4 * 4 + i];
        g_csrs[atomicAdd(&g_rowptr[d], 1)] = s;
    }
}

// ---------------- fused MLP: h0 = relu(x@W1+b1)@W2 + b2, write u seeds ------
// FFMA2 with node-pairs in the packed lanes: acc[h][p] += (a_n2p,a_n2p+1)*(w_h,w_h).
// W1 tile staged DUPLICATED (Ws2) with a skewed layout -> conflict-free, no packs.
__global__ __launch_bounds__(256, 2)
void mlp_fused_kernel(const float* __restrict__ x,
                      const float* __restrict__ W1,
                      const float* __restrict__ b1,
                      const float* __restrict__ W2,
                      const float* __restrict__ b2, int n) {
    __shared__ float sh[8192];     // 32 KB: phase A [As 16x256 | Ws2 16x144]; phase B Hs 128x64
    __shared__ float W2s[HIDDEN * CLASSES];  // 8 KB
    __shared__ float b2s[CLASSES];
    float* As  = sh;               // [k][node] : k*256+node
    float* Ws2 = sh + 4096;        // [k][dup-hid skewed] : k*144 + f(g) + 2j

    int tid = threadIdx.x;
    int tx  = tid & 7;             // hidden group (8 hid)
    int ty  = tid >> 3;            // node group (8 nodes)
    int bn  = blockIdx.x * 256;

    for (int i = tid; i < HIDDEN * CLASSES; i += 256) W2s[i] = W2[i];
    if (tid < CLASSES) b2s[tid] = b2[tid];

    int anode = tid >> 2;
    int ak    = (tid & 3) * 4;
    int wk    = tid >> 4;          // 0..15
    int wc    = (tid & 15) * 4;    // hid 0..60

    // skew offsets: f(g) = g*16 + (g>>1)*4 floats (distinct 16B slots mod 128B)
    int wg   = wc >> 3;
    int woff = wg * 16 + (wg >> 1) * 4 + (wc & 7) * 2;
    int bo   = tx * 16 + (tx >> 1) * 4;

    unsigned long long acc[8][4];  // [hid j][node-pair p]
    #pragma unroll
    for (int i = 0; i < 8; i++)
        #pragma unroll
        for (int j = 0; j < 4; j++) acc[i][j] = 0ULL;

    for (int k0 = 0; k0 < FEATS; k0 += 16) {
        #pragma unroll
        for (int r = 0; r < 4; r++) {
            int nd = anode + r * 64;
            int node = bn + nd;
            float4 av = make_float4(0.f, 0.f, 0.f, 0.f);
            if (node < n)
                av = *(const float4*)&x[(size_t)node * FEATS + k0 + ak];
            As[(ak + 0) * 256 + nd] = av.x;
            As[(ak + 1) * 256 + nd] = av.y;
            As[(ak + 2) * 256 + nd] = av.z;
            As[(ak + 3) * 256 + nd] = av.w;
        }
        {   // stage W1 duplicated: (w,w) pairs, skewed
            float4 wv = *(const float4*)&W1[(size_t)(k0 + wk) * HIDDEN + wc];
            float4 d0 = make_float4(wv.x, wv.x, wv.y, wv.y);
            float4 d1 = make_float4(wv.z, wv.z, wv.w, wv.w);
            *(float4*)&Ws2[wk * 144 + woff]     = d0;
            *(float4*)&Ws2[wk * 144 + woff + 4] = d1;
        }
        __syncthreads();
        #pragma unroll
        for (int k = 0; k < 16; k++) {
            ulonglong2 ap01 = *(const ulonglong2*)&As[k * 256 + ty * 8];
            ulonglong2 ap23 = *(const ulonglong2*)&As[k * 256 + ty * 8 + 4];
            ulonglong2 b01 = *(const ulonglong2*)&Ws2[k * 144 + bo];
            ulonglong2 b23 = *(const ulonglong2*)&Ws2[k * 144 + bo + 4];
            ulonglong2 b45 = *(const ulonglong2*)&Ws2[k * 144 + bo + 8];
            ulonglong2 b67 = *(const ulonglong2*)&Ws2[k * 144 + bo + 12];
            unsigned long long bs[8] = {b01.x, b01.y, b23.x, b23.y,
                                        b45.x, b45.y, b67.x, b67.y};
            #pragma unroll
            for (int j = 0; j < 8; j++) {
                ffma2(acc[j][0], ap01.x, bs[j]);
                ffma2(acc[j][1], ap01.y, bs[j]);
                ffma2(acc[j][2], ap23.x, bs[j]);
                ffma2(acc[j][3], ap23.y, bs[j]);
            }
        }
        __syncthreads();
    }

    float4 bb0 = *(const float4*)&b1[tx * 8];
    float4 bb1 = *(const float4*)&b1[tx * 8 + 4];
    float bbv[8] = {bb0.x, bb0.y, bb0.z, bb0.w, bb1.x, bb1.y, bb1.z, bb1.w};
    int lane = tid & 31;
    int w    = tid >> 5;
    float* h0u = (float*)g_h0u;
    __half* uA = (__half*)g_uhA;

    #pragma unroll 1
    for (int h = 0; h < 2; h++) {
        if ((ty >> 4) == h) {
            int lty = ty & 15;
            #pragma unroll
            for (int i = 0; i < 8; i++) {
                int ln = lty * 8 + i;
                if (bn + h * 128 + ln < n) {
                    float* hr = &sh[ln * 64 + tx * 8];
                    #pragma unroll
                    for (int j = 0; j < 8; j++) {
                        float2 q = unpack2(acc[j][i >> 1]);
                        float v = (i & 1) ? q.y : q.x;
                        hr[j] = fmaxf(v + bbv[j], 0.f);
                    }
                }
            }
        }
        __syncthreads();
        #pragma unroll 1
        for (int t = 0; t < 16; t++) {
            int ln = w * 16 + t;
            int node = bn + h * 128 + ln;
            if (node < n) {
                float s = 0.f;
                #pragma unroll
                for (int k4 = 0; k4 < 16; k4++) {
                    float4 hv = *(const float4*)&sh[ln * 64 + k4 * 4];
                    s = fmaf(hv.x, W2s[(k4 * 4 + 0) * CLASSES + lane], s);
                    s = fmaf(hv.y, W2s[(k4 * 4 + 1) * CLASSES + lane], s);
                    s = fmaf(hv.z, W2s[(k4 * 4 + 2) * CLASSES + lane], s);
                    s = fmaf(hv.w, W2s[(k4 * 4 + 3) * CLASSES + lane], s);
                }
                s += b2s[lane];
                float rv = g_rinv[node];
                h0u[(size_t)node * CLASSES + lane] = 0.1f * rv * s;
                uA[(size_t)node * CLASSES + lane]  = __float2half_rn(rv * s);
            }
        }
        __syncthreads();
    }
}

// ---------------- propagation (u-space, fp16 rows, fp32 accumulate) ---------
// One warp per dst node: 8 edge-groups x 4 lanes; lane owns one uint4 (8 halves).
__global__ void prop_kernel(int parity, float* __restrict__ ext_out, int n) {
    int gw = (blockIdx.x * blockDim.x + threadIdx.x) >> 5;
    if (gw >= n) return;
    int lane = threadIdx.x & 31;
    int grp  = lane >> 2;
    int c    = lane & 3;

    const uint4* u_in = parity ? g_uhB : g_uhA;
    int beg = gw ? __ldg(&g_rowptr[gw - 1]) : 0;
    int end = __ldg(&g_rowptr[gw]);

    float4 lo0 = make_float4(0.f, 0.f, 0.f, 0.f), hi0 = lo0;
    float4 lo1 = lo0, hi1 = lo0;
    int i = beg + grp;
    for (; i + 8 < end; i += 16) {
        int s0 = __ldg(&g_csrs[i]);
        int s1 = __ldg(&g_csrs[i + 8]);
        uint4 v0 = __ldg(&u_in[(size_t)s0 * 4 + c]);
        uint4 v1 = __ldg(&u_in[(size_t)s1 * 4 + c]);
        acc8(lo0, hi0, v0);
        acc8(lo1, hi1, v1);
    }
    if (i < end) {
        int s0 = __ldg(&g_csrs[i]);
        uint4 v0 = __ldg(&u_in[(size_t)s0 * 4 + c]);
        acc8(lo0, hi0, v0);
    }
    lo0.x += lo1.x; lo0.y += lo1.y; lo0.z += lo1.z; lo0.w += lo1.w;
    hi0.x += hi1.x; hi0.y += hi1.y; hi0.z += hi1.z; hi0.w += hi1.w;

    #pragma unroll
    for (int off = 4; off <= 16; off <<= 1) {
        lo0.x += __shfl_xor_sync(0xffffffffu, lo0.x, off);
        lo0.y += __shfl_xor_sync(0xffffffffu, lo0.y, off);
        lo0.z += __shfl_xor_sync(0xffffffffu, lo0.z, off);
        lo0.w += __shfl_xor_sync(0xffffffffu, lo0.w, off);
        hi0.x += __shfl_xor_sync(0xffffffffu, hi0.x, off);
        hi0.y += __shfl_xor_sync(0xffffffffu, hi0.y, off);
        hi0.z += __shfl_xor_sync(0xffffffffu, hi0.z, off);
        hi0.w += __shfl_xor_sync(0xffffffffu, hi0.w, off);
    }
    if (grp == 0) {
        float2 cf = __ldg(&g_coef[gw]);
        float4 z0 = __ldg(&g_h0u[(size_t)gw * 8 + c * 2]);
        float4 z1 = __ldg(&g_h0u[(size_t)gw * 8 + c * 2 + 1]);
        float4 o0, o1;
        o0.x = fmaf(cf.x, lo0.x, z0.x);
        o0.y = fmaf(cf.x, lo0.y, z0.y);
        o0.z = fmaf(cf.x, lo0.z, z0.z);
        o0.w = fmaf(cf.x, lo0.w, z0.w);
        o1.x = fmaf(cf.x, hi0.x, z1.x);
        o1.y = fmaf(cf.x, hi0.y, z1.y);
        o1.z = fmaf(cf.x, hi0.z, z1.z);
        o1.w = fmaf(cf.x, hi0.w, z1.w);
        if (ext_out) {  // final iteration: back to h-space, fp32 out
            o0.x *= cf.y; o0.y *= cf.y; o0.z *= cf.y; o0.w *= cf.y;
            o1.x *= cf.y; o1.y *= cf.y; o1.z *= cf.y; o1.w *= cf.y;
            ((float4*)ext_out)[(size_t)gw * 8 + c * 2]     = o0;
            ((float4*)ext_out)[(size_t)gw * 8 + c * 2 + 1] = o1;
        } else {
            uint4* u_out = parity ? g_uhA : g_uhB;
            u_out[(size_t)gw * 4 + c] = pack8(o0, o1);
        }
    }
}

// ---------------- host driver -----------------------------------------------
extern "C" void kernel_launch(void* const* d_in, const int* in_sizes, int n_in,
                              void* d_out, int out_size) {
    const float* x     = (const float*)d_in[0];
    const int*   edges = (const int*)d_in[1];     // int32 (JAX x64 off)
    const float* W1    = (const float*)d_in[2];
    const float* b1    = (const float*)d_in[3];
    const float* W2    = (const float*)d_in[4];
    const float* b2    = (const float*)d_in[5];

    int n = in_sizes[0] / FEATS;
    int E = in_sizes[1] / 2;

    const int TB = 256;
    int nchunks = (n + SCAN_CHUNK - 1) / SCAN_CHUNK;
    int E4 = (E >> 2) ? (E >> 2) : 1;
    zero_kernel<<<(n + TB - 1) / TB, TB>>>(n);
    deg_kernel<<<(E4 + TB - 1) / TB, TB>>>(edges, E);
    scan_block_kernel<<<nchunks, SCAN_CHUNK>>>(n);
    scan_sums_kernel<<<1, 32>>>(nchunks, n);
    scan_add_kernel<<<(n + SCAN_CHUNK - 1) / SCAN_CHUNK, SCAN_CHUNK>>>(n);
    fill_kernel<<<(E4 + TB - 1) / TB, TB>>>(edges, E);

    mlp_fused_kernel<<<(n + 255) / 256, 256>>>(x, W1, b1, W2, b2, n);

    int prop_blocks = (n * 32 + TB - 1) / TB;   // one warp per node
    for (int it = 0; it < 10; it++) {
        prop_kernel<<<prop_blocks, TB>>>(it & 1,
                                         (it == 9) ? (float*)d_out : nullptr,
                                         n);
    }
}

// round 16
// speedup vs baseline: 1.1182x; 1.0035x over previous
#include <cuda_runtime.h>
#include <cuda_fp16.h>

// ---------------- problem constants ----------------------------------------
#define NMAX   100000
#define EMAX   3200000
#define FEATS  512
#define HIDDEN 64
#define CLASSES 32
#define SCAN_CHUNK 1024
#define MAX_CHUNKS ((NMAX + SCAN_CHUNK - 1) / SCAN_CHUNK)

// ---------------- scratch (static device memory; no allocation) ------------
__device__ int    g_deg[NMAX];
__device__ int    g_rowptr[NMAX + 1];     // doubles as fill cursor
__device__ int    g_bsum[MAX_CHUNKS];
__device__ int    g_boff[MAX_CHUNKS];
__device__ int    g_csrs[EMAX];           // src only (u-space: no weights)
__device__ float  g_rinv[NMAX];
__device__ float2 g_coef[NMAX];           // {0.9/deg, sqrt(deg)}
__device__ uint4  g_h0uh[(size_t)NMAX * 4];     // 0.1*rinv*h0 as half8 rows
__device__ uint4  g_uhA[(size_t)NMAX * 4];      // u as half8 rows (64 B)
__device__ uint4  g_uhB[(size_t)NMAX * 4];

// ---------------- f32x2 packed-FMA helpers (sm_100+) ------------------------
__device__ __forceinline__ void ffma2(unsigned long long& d,
                                      unsigned long long a,
                                      unsigned long long b) {
    asm("fma.rn.f32x2 %0, %1, %2, %0;" : "+l"(d) : "l"(a), "l"(b));
}
__device__ __forceinline__ float2 unpack2(unsigned long long v) {
    float2 f;
    asm("mov.b64 {%0, %1}, %2;" : "=f"(f.x), "=f"(f.y) : "l"(v));
    return f;
}

// half8 helpers
__device__ __forceinline__ void acc8(float4& lo, float4& hi, uint4 v) {
    float2 p;
    p = __half22float2(*(__half2*)&v.x); lo.x += p.x; lo.y += p.y;
    p = __half22float2(*(__half2*)&v.y); lo.z += p.x; lo.w += p.y;
    p = __half22float2(*(__half2*)&v.z); hi.x += p.x; hi.y += p.y;
    p = __half22float2(*(__half2*)&v.w); hi.z += p.x; hi.w += p.y;
}
__device__ __forceinline__ void cvt8(float4& lo, float4& hi, uint4 v) {
    float2 p;
    p = __half22float2(*(__half2*)&v.x); lo.x = p.x; lo.y = p.y;
    p = __half22float2(*(__half2*)&v.y); lo.z = p.x; lo.w = p.y;
    p = __half22float2(*(__half2*)&v.z); hi.x = p.x; hi.y = p.y;
    p = __half22float2(*(__half2*)&v.w); hi.z = p.x; hi.w = p.y;
}
__device__ __forceinline__ uint4 pack8(float4 lo, float4 hi) {
    uint4 r;
    *(__half2*)&r.x = __floats2half2_rn(lo.x, lo.y);
    *(__half2*)&r.y = __floats2half2_rn(lo.z, lo.w);
    *(__half2*)&r.z = __floats2half2_rn(hi.x, hi.y);
    *(__half2*)&r.w = __floats2half2_rn(hi.z, hi.w);
    return r;
}

// ---------------- setup kernels ---------------------------------------------
__global__ void zero_kernel(int n) {
    int i = blockIdx.x * blockDim.x + threadIdx.x;
    if (i < n) g_deg[i] = 0;
}

__global__ void deg_kernel(const int* __restrict__ edges, int E) {
    int i = blockIdx.x * blockDim.x + threadIdx.x;
    int E4 = E >> 2;
    const int4* dst4 = (const int4*)(edges + E);
    if (i < E4) {
        int4 d = __ldg(&dst4[i]);
        atomicAdd(&g_deg[d.x], 1);
        atomicAdd(&g_deg[d.y], 1);
        atomicAdd(&g_deg[d.z], 1);
        atomicAdd(&g_deg[d.w], 1);
    }
    int tail = E & 3;
    if (i < tail) atomicAdd(&g_deg[edges[E + E4 * 4 + i]], 1);
}

__global__ void scan_block_kernel(int n) {
    __shared__ int wsum[32];
    int tid = threadIdx.x, lane = tid & 31, wid = tid >> 5;
    int i = blockIdx.x * SCAN_CHUNK + tid;
    int v = (i < n) ? g_deg[i] : 0;
    if (i < n) {
        float fd = (float)max(v, 1);
        g_rinv[i] = rsqrtf(fd);
        g_coef[i] = make_float2(0.9f / fd, sqrtf(fd));
    }
    int s = v;
    #pragma unroll
    for (int o = 1; o < 32; o <<= 1) {
        int t = __shfl_up_sync(0xffffffffu, s, o);
        if (lane >= o) s += t;
    }
    if (lane == 31) wsum[wid] = s;
    __syncthreads();
    if (wid == 0) {
        int ws = wsum[lane];
        #pragma unroll
        for (int o = 1; o < 32; o <<= 1) {
            int t = __shfl_up_sync(0xffffffffu, ws, o);
            if (lane >= o) ws += t;
        }
        wsum[lane] = ws;
    }
    __syncthreads();
    int incl = s + (wid ? wsum[wid - 1] : 0);
    if (i < n) g_rowptr[i] = incl - v;
    if (tid == SCAN_CHUNK - 1) g_bsum[blockIdx.x] = incl;
}

__global__ void scan_sums_kernel(int nb, int n) {
    int lane = threadIdx.x;
    int carry = 0;
    for (int base = 0; base < nb; base += 32) {
        int v = (base + lane < nb) ? g_bsum[base + lane] : 0;
        int s = v;
        #pragma unroll
        for (int o = 1; o < 32; o <<= 1) {
            int t = __shfl_up_sync(0xffffffffu, s, o);
            if (lane >= o) s += t;
        }
        if (base + lane < nb) g_boff[base + lane] = carry + s - v;
        carry += __shfl_sync(0xffffffffu, s, 31);
    }
    if (lane == 0) g_rowptr[n] = carry;
}

__global__ void scan_add_kernel(int n) {
    int i = blockIdx.x * blockDim.x + threadIdx.x;
    if (i < n) g_rowptr[i] += g_boff[i >> 10];
}

__global__ void fill_kernel(const int* __restrict__ edges, int E) {
    int i = blockIdx.x * blockDim.x + threadIdx.x;
    int E4 = E >> 2;
    const int4* src4 = (const int4*)edges;
    const int4* dst4 = (const int4*)(edges + E);
    if (i < E4) {
        int4 s = __ldg(&src4[i]);
        int4 d = __ldg(&dst4[i]);
        g_csrs[atomicAdd(&g_rowptr[d.x], 1)] = s.x;
        g_csrs[atomicAdd(&g_rowptr[d.y], 1)] = s.y;
        g_csrs[atomicAdd(&g_rowptr[d.z], 1)] = s.z;
        g_csrs[atomicAdd(&g_rowptr[d.w], 1)] = s.w;
    }
    int tail = E & 3;
    if (i < tail) {
        int s = edges[E4 * 4 + i];
        int d = edges[E + E4 * 4 + i];
        g_csrs[atomicAdd(&g_rowptr[d], 1)] = s;
    }
}

// ---------------- fused MLP v3: 128-node tile, 3 CTAs/SM --------------------
// Thread = 8 nodes x 4 hid (32 acc regs). tx = tid&15 (4 hid), ty = tid>>4 (8 nodes).
#define AS_STRIDE 132
#define WS_OFF    2112            // floats (16B aligned)
#define WS_STRIDE 144
__global__ __launch_bounds__(256, 3)
void mlp_fused_kernel(const float* __restrict__ x,
                      const float* __restrict__ W1,
                      const float* __restrict__ b1,
                      const float* __restrict__ W2,
                      const float* __restrict__ b2, int n) {
    __shared__ float sh[8192];               // phase A: As+Ws2 (17.3KB); phase B: Hs 128x64
    __shared__ float W2s[HIDDEN * CLASSES];  // 8 KB
    __shared__ float b2s[CLASSES];

    int tid = threadIdx.x;
    int tx  = tid & 15;            // hid group (4 hid)
    int ty  = tid >> 4;            // node group (8 nodes)
    int bn  = blockIdx.x * 128;

    for (int i = tid; i < HIDDEN * CLASSES; i += 256) W2s[i] = W2[i];
    if (tid < CLASSES) b2s[tid] = b2[tid];

    // tile loaders
    int anode = tid >> 2;          // 0..63 (+64 for second)
    int ak    = (tid & 3) * 4;     // k 0,4,8,12
    int wk    = tid >> 4;          // 0..15
    int wc    = (tid & 15) * 4;    // hid 0..60
    int wgrp  = wc >> 2;           // = tid&15
    int woff  = wgrp * 8 + (wgrp >> 2) * 4;   // dup-skew (floats, 16B granules)
    int bo    = tx * 8 + (tx >> 2) * 4;       // reader offset (same formula)

    unsigned long long acc[4][4];  // [hid j][node-pair p]
    #pragma unroll
    for (int j = 0; j < 4; j++)
        #pragma unroll
        for (int p = 0; p < 4; p++) acc[j][p] = 0ULL;

    for (int k0 = 0; k0 < FEATS; k0 += 16) {
        // stage As [k][node], stride 132
        {
            int n0 = bn + anode, n1 = bn + anode + 64;
            float4 a0 = make_float4(0.f, 0.f, 0.f, 0.f), a1 = a0;
            if (n0 < n) a0 = *(const float4*)&x[(size_t)n0 * FEATS + k0 + ak];
            if (n1 < n) a1 = *(const float4*)&x[(size_t)n1 * FEATS + k0 + ak];
            sh[(ak + 0) * AS_STRIDE + anode] = a0.x;
            sh[(ak + 1) * AS_STRIDE + anode] = a0.y;
            sh[(ak + 2) * AS_STRIDE + anode] = a0.z;
            sh[(ak + 3) * AS_STRIDE + anode] = a0.w;
            sh[(ak + 0) * AS_STRIDE + anode + 64] = a1.x;
            sh[(ak + 1) * AS_STRIDE + anode + 64] = a1.y;
            sh[(ak + 2) * AS_STRIDE + anode + 64] = a1.z;
            sh[(ak + 3) * AS_STRIDE + anode + 64] = a1.w;
        }
        // stage Ws2 duplicated (w,w) pairs, skewed
        {
            float4 wv = *(const float4*)&W1[(size_t)(k0 + wk) * HIDDEN + wc];
            *(float4*)&sh[WS_OFF + wk * WS_STRIDE + woff] =
                make_float4(wv.x, wv.x, wv.y, wv.y);
            *(float4*)&sh[WS_OFF + wk * WS_STRIDE + woff + 4] =
                make_float4(wv.z, wv.z, wv.w, wv.w);
        }
        __syncthreads();
        #pragma unroll
        for (int k = 0; k < 16; k++) {
            ulonglong2 apA = *(const ulonglong2*)&sh[k * AS_STRIDE + ty * 8];
            ulonglong2 apB = *(const ulonglong2*)&sh[k * AS_STRIDE + ty * 8 + 4];
            ulonglong2 w01 = *(const ulonglong2*)&sh[WS_OFF + k * WS_STRIDE + bo];
            ulonglong2 w23 = *(const ulonglong2*)&sh[WS_OFF + k * WS_STRIDE + bo + 4];
            unsigned long long ws[4] = {w01.x, w01.y, w23.x, w23.y};
            #pragma unroll
            for (int j = 0; j < 4; j++) {
                ffma2(acc[j][0], apA.x, ws[j]);
                ffma2(acc[j][1], apA.y, ws[j]);
                ffma2(acc[j][2], apB.x, ws[j]);
                ffma2(acc[j][3], apB.y, ws[j]);
            }
        }
        __syncthreads();
    }

    // epilogue: bias+relu -> Hs[node][hid] (float4 stores)
    float4 bb = *(const float4*)&b1[tx * 4];
    #pragma unroll
    for (int i = 0; i < 8; i++) {
        int p = i >> 1;
        float2 q0 = unpack2(acc[0][p]);
        float2 q1 = unpack2(acc[1][p]);
        float2 q2 = unpack2(acc[2][p]);
        float2 q3 = unpack2(acc[3][p]);
        float4 hv;
        if (i & 1) hv = make_float4(q0.y, q1.y, q2.y, q3.y);
        else       hv = make_float4(q0.x, q1.x, q2.x, q3.x);
        hv.x = fmaxf(hv.x + bb.x, 0.f);
        hv.y = fmaxf(hv.y + bb.y, 0.f);
        hv.z = fmaxf(hv.z + bb.z, 0.f);
        hv.w = fmaxf(hv.w + bb.w, 0.f);
        *(float4*)&sh[(ty * 8 + i) * 64 + tx * 4] = hv;
    }
    __syncthreads();

    // W2 phase: warp w handles 16 nodes; lane = class
    int lane = tid & 31;
    int w    = tid >> 5;
    __half* h0h = (__half*)g_h0uh;
    __half* uA  = (__half*)g_uhA;
    #pragma unroll 1
    for (int t = 0; t < 16; t++) {
        int ln = w * 16 + t;
        int node = bn + ln;
        if (node < n) {
            float s = 0.f;
            #pragma unroll
            for (int k4 = 0; k4 < 16; k4++) {
                float4 hv = *(const float4*)&sh[ln * 64 + k4 * 4];
                s = fmaf(hv.x, W2s[(k4 * 4 + 0) * CLASSES + lane], s);
                s = fmaf(hv.y, W2s[(k4 * 4 + 1) * CLASSES + lane], s);
                s = fmaf(hv.z, W2s[(k4 * 4 + 2) * CLASSES + lane], s);
                s = fmaf(hv.w, W2s[(k4 * 4 + 3) * CLASSES + lane], s);
            }
            s += b2s[lane];
            float rv = g_rinv[node];
            h0h[(size_t)node * CLASSES + lane] = __float2half_rn(0.1f * rv * s);
            uA[(size_t)node * CLASSES + lane]  = __float2half_rn(rv * s);
        }
    }
}

// ---------------- propagation (u-space, fp16 rows, fp32 accumulate) ---------
__global__ void prop_kernel(int parity, float* __restrict__ ext_out, int n) {
    int gw = (blockIdx.x * blockDim.x + threadIdx.x) >> 5;
    if (gw >= n) return;
    int lane = threadIdx.x & 31;
    int grp  = lane >> 2;
    int c    = lane & 3;

    const uint4* u_in = parity ? g_uhB : g_uhA;
    int beg = gw ? __ldg(&g_rowptr[gw - 1]) : 0;
    int end = __ldg(&g_rowptr[gw]);

    float4 lo0 = make_float4(0.f, 0.f, 0.f, 0.f), hi0 = lo0;
    float4 lo1 = lo0, hi1 = lo0;
    int i = beg + grp;
    for (; i + 8 < end; i += 16) {
        int s0 = __ldg(&g_csrs[i]);
        int s1 = __ldg(&g_csrs[i + 8]);
        uint4 v0 = __ldg(&u_in[(size_t)s0 * 4 + c]);
        uint4 v1 = __ldg(&u_in[(size_t)s1 * 4 + c]);
        acc8(lo0, hi0, v0);
        acc8(lo1, hi1, v1);
    }
    if (i < end) {
        int s0 = __ldg(&g_csrs[i]);
        uint4 v0 = __ldg(&u_in[(size_t)s0 * 4 + c]);
        acc8(lo0, hi0, v0);
    }
    lo0.x += lo1.x; lo0.y += lo1.y; lo0.z += lo1.z; lo0.w += lo1.w;
    hi0.x += hi1.x; hi0.y += hi1.y; hi0.z += hi1.z; hi0.w += hi1.w;

    #pragma unroll
    for (int off = 4; off <= 16; off <<= 1) {
        lo0.x += __shfl_xor_sync(0xffffffffu, lo0.x, off);
        lo0.y += __shfl_xor_sync(0xffffffffu, lo0.y, off);
        lo0.z += __shfl_xor_sync(0xffffffffu, lo0.z, off);
        lo0.w += __shfl_xor_sync(0xffffffffu, lo0.w, off);
        hi0.x += __shfl_xor_sync(0xffffffffu, hi0.x, off);
        hi0.y += __shfl_xor_sync(0xffffffffu, hi0.y, off);
        hi0.z += __shfl_xor_sync(0xffffffffu, hi0.z, off);
        hi0.w += __shfl_xor_sync(0xffffffffu, hi0.w, off);
    }
    if (grp == 0) {
        float2 cf = __ldg(&g_coef[gw]);
        uint4 zv = __ldg(&g_h0uh[(size_t)gw * 4 + c]);
        float4 z0, z1;
        cvt8(z0, z1, zv);
        float4 o0, o1;
        o0.x = fmaf(cf.x, lo0.x, z0.x);
        o0.y = fmaf(cf.x, lo0.y, z0.y);
        o0.z = fmaf(cf.x, lo0.z, z0.z);
        o0.w = fmaf(cf.x, lo0.w, z0.w);
        o1.x = fmaf(cf.x, hi0.x, z1.x);
        o1.y = fmaf(cf.x, hi0.y, z1.y);
        o1.z = fmaf(cf.x, hi0.z, z1.z);
        o1.w = fmaf(cf.x, hi0.w, z1.w);
        if (ext_out) {  // final iteration: back to h-space, fp32 out
            o0.x *= cf.y; o0.y *= cf.y; o0.z *= cf.y; o0.w *= cf.y;
            o1.x *= cf.y; o1.y *= cf.y; o1.z *= cf.y; o1.w *= cf.y;
            ((float4*)ext_out)[(size_t)gw * 8 + c * 2]     = o0;
            ((float4*)ext_out)[(size_t)gw * 8 + c * 2 + 1] = o1;
        } else {
            uint4* u_out = parity ? g_uhA : g_uhB;
            u_out[(size_t)gw * 4 + c] = pack8(o0, o1);
        }
    }
}

// ---------------- host driver -----------------------------------------------
extern "C" void kernel_launch(void* const* d_in, const int* in_sizes, int n_in,
                              void* d_out, int out_size) {
    const float* x     = (const float*)d_in[0];
    const int*   edges = (const int*)d_in[1];     // int32 (JAX x64 off)
    const float* W1    = (const float*)d_in[2];
    const float* b1    = (const float*)d_in[3];
    const float* W2    = (const float*)d_in[4];
    const float* b2    = (const float*)d_in[5];

    int n = in_sizes[0] / FEATS;
    int E = in_sizes[1] / 2;

    const int TB = 256;
    int nchunks = (n + SCAN_CHUNK - 1) / SCAN_CHUNK;
    int E4 = (E >> 2) ? (E >> 2) : 1;
    zero_kernel<<<(n + TB - 1) / TB, TB>>>(n);
    deg_kernel<<<(E4 + TB - 1) / TB, TB>>>(edges, E);
    scan_block_kernel<<<nchunks, SCAN_CHUNK>>>(n);
    scan_sums_kernel<<<1, 32>>>(nchunks, n);
    scan_add_kernel<<<(n + SCAN_CHUNK - 1) / SCAN_CHUNK, SCAN_CHUNK>>>(n);
    fill_kernel<<<(E4 + TB - 1) / TB, TB>>>(edges, E);

    mlp_fused_kernel<<<(n + 127) / 128, 256>>>(x, W1, b1, W2, b2, n);

    int prop_blocks = (n * 32 + TB - 1) / TB;   // one warp per node
    for (int it = 0; it < 10; it++) {
        prop_kernel<<<prop_blocks, TB>>>(it & 1,
                                         (it == 9) ? (float*)d_out : nullptr,
                                         n);
    }
}

// round 17
// speedup vs baseline: 1.1410x; 1.0203x over previous
#include <cuda_runtime.h>
#include <cuda_fp16.h>

// ---------------- problem constants ----------------------------------------
#define NMAX   100000
#define EMAX   3200000
#define FEATS  512
#define HIDDEN 64
#define CLASSES 32
#define SCAN_CHUNK 1024
#define MAX_CHUNKS ((NMAX + SCAN_CHUNK - 1) / SCAN_CHUNK)

// ---------------- scratch (static device memory; no allocation) ------------
__device__ int    g_deg[NMAX];
__device__ int    g_rowptr[NMAX + 1];     // doubles as fill cursor
__device__ int    g_bsum[MAX_CHUNKS];
__device__ int    g_boff[MAX_CHUNKS];
__device__ int    g_csrs[EMAX];           // src only (u-space: no weights)
__device__ float  g_rinv[NMAX];
__device__ float2 g_coef[NMAX];           // {0.9/deg, sqrt(deg)}
__device__ uint4  g_h0uh[(size_t)NMAX * 4];     // 0.1*rinv*h0 as half8 rows
__device__ uint4  g_uhA[(size_t)NMAX * 4];      // u as half8 rows (64 B)
__device__ uint4  g_uhB[(size_t)NMAX * 4];

// ---------------- f32x2 packed-FMA helpers (sm_100+) ------------------------
__device__ __forceinline__ void ffma2(unsigned long long& d,
                                      unsigned long long a,
                                      unsigned long long b) {
    asm("fma.rn.f32x2 %0, %1, %2, %0;" : "+l"(d) : "l"(a), "l"(b));
}
__device__ __forceinline__ float2 unpack2(unsigned long long v) {
    float2 f;
    asm("mov.b64 {%0, %1}, %2;" : "=f"(f.x), "=f"(f.y) : "l"(v));
    return f;
}

// half8 helpers
__device__ __forceinline__ void acc8(float4& lo, float4& hi, uint4 v) {
    float2 p;
    p = __half22float2(*(__half2*)&v.x); lo.x += p.x; lo.y += p.y;
    p = __half22float2(*(__half2*)&v.y); lo.z += p.x; lo.w += p.y;
    p = __half22float2(*(__half2*)&v.z); hi.x += p.x; hi.y += p.y;
    p = __half22float2(*(__half2*)&v.w); hi.z += p.x; hi.w += p.y;
}
__device__ __forceinline__ void cvt8(float4& lo, float4& hi, uint4 v) {
    float2 p;
    p = __half22float2(*(__half2*)&v.x); lo.x = p.x; lo.y = p.y;
    p = __half22float2(*(__half2*)&v.y); lo.z = p.x; lo.w = p.y;
    p = __half22float2(*(__half2*)&v.z); hi.x = p.x; hi.y = p.y;
    p = __half22float2(*(__half2*)&v.w); hi.z = p.x; hi.w = p.y;
}
__device__ __forceinline__ uint4 pack8(float4 lo, float4 hi) {
    uint4 r;
    *(__half2*)&r.x = __floats2half2_rn(lo.x, lo.y);
    *(__half2*)&r.y = __floats2half2_rn(lo.z, lo.w);
    *(__half2*)&r.z = __floats2half2_rn(hi.x, hi.y);
    *(__half2*)&r.w = __floats2half2_rn(hi.z, hi.w);
    return r;
}

// ---------------- setup kernels ---------------------------------------------
__global__ void zero_kernel(int n) {
    int i = blockIdx.x * blockDim.x + threadIdx.x;
    if (i < n) g_deg[i] = 0;
}

__global__ void deg_kernel(const int* __restrict__ edges, int E) {
    int i = blockIdx.x * blockDim.x + threadIdx.x;
    int E4 = E >> 2;
    const int4* dst4 = (const int4*)(edges + E);
    if (i < E4) {
        int4 d = __ldg(&dst4[i]);
        atomicAdd(&g_deg[d.x], 1);
        atomicAdd(&g_deg[d.y], 1);
        atomicAdd(&g_deg[d.z], 1);
        atomicAdd(&g_deg[d.w], 1);
    }
    int tail = E & 3;
    if (i < tail) atomicAdd(&g_deg[edges[E + E4 * 4 + i]], 1);
}

__global__ void scan_block_kernel(int n) {
    __shared__ int wsum[32];
    int tid = threadIdx.x, lane = tid & 31, wid = tid >> 5;
    int i = blockIdx.x * SCAN_CHUNK + tid;
    int v = (i < n) ? g_deg[i] : 0;
    if (i < n) {
        float fd = (float)max(v, 1);
        g_rinv[i] = rsqrtf(fd);
        g_coef[i] = make_float2(0.9f / fd, sqrtf(fd));
    }
    int s = v;
    #pragma unroll
    for (int o = 1; o < 32; o <<= 1) {
        int t = __shfl_up_sync(0xffffffffu, s, o);
        if (lane >= o) s += t;
    }
    if (lane == 31) wsum[wid] = s;
    __syncthreads();
    if (wid == 0) {
        int ws = wsum[lane];
        #pragma unroll
        for (int o = 1; o < 32; o <<= 1) {
            int t = __shfl_up_sync(0xffffffffu, ws, o);
            if (lane >= o) ws += t;
        }
        wsum[lane] = ws;
    }
    __syncthreads();
    int incl = s + (wid ? wsum[wid - 1] : 0);
    if (i < n) g_rowptr[i] = incl - v;
    if (tid == SCAN_CHUNK - 1) g_bsum[blockIdx.x] = incl;
}

__global__ void scan_sums_kernel(int nb, int n) {
    int lane = threadIdx.x;
    int carry = 0;
    for (int base = 0; base < nb; base += 32) {
        int v = (base + lane < nb) ? g_bsum[base + lane] : 0;
        int s = v;
        #pragma unroll
        for (int o = 1; o < 32; o <<= 1) {
            int t = __shfl_up_sync(0xffffffffu, s, o);
            if (lane >= o) s += t;
        }
        if (base + lane < nb) g_boff[base + lane] = carry + s - v;
        carry += __shfl_sync(0xffffffffu, s, 31);
    }
    if (lane == 0) g_rowptr[n] = carry;
}

__global__ void scan_add_kernel(int n) {
    int i = blockIdx.x * blockDim.x + threadIdx.x;
    if (i < n) g_rowptr[i] += g_boff[i >> 10];
}

__global__ void fill_kernel(const int* __restrict__ edges, int E) {
    int i = blockIdx.x * blockDim.x + threadIdx.x;
    int E4 = E >> 2;
    const int4* src4 = (const int4*)edges;
    const int4* dst4 = (const int4*)(edges + E);
    if (i < E4) {
        int4 s = __ldg(&src4[i]);
        int4 d = __ldg(&dst4[i]);
        g_csrs[atomicAdd(&g_rowptr[d.x], 1)] = s.x;
        g_csrs[atomicAdd(&g_rowptr[d.y], 1)] = s.y;
        g_csrs[atomicAdd(&g_rowptr[d.z], 1)] = s.z;
        g_csrs[atomicAdd(&g_rowptr[d.w], 1)] = s.w;
    }
    int tail = E & 3;
    if (i < tail) {
        int s = edges[E4 * 4 + i];
        int d = edges[E + E4 * 4 + i];
        g_csrs[atomicAdd(&g_rowptr[d], 1)] = s;
    }
}

// ---------------- fused MLP v4: 128-node tile + register double-buffer ------
// Thread = 8 nodes x 4 hid. Prefetch next k-tile's x/W1 into registers while
// computing the current tile -> hides the DRAM latency that bounded v2/v3.
#define AS_STRIDE 132
#define WS_OFF    2112            // floats (16B aligned)
#define WS_STRIDE 144
__global__ __launch_bounds__(256, 3)
void mlp_fused_kernel(const float* __restrict__ x,
                      const float* __restrict__ W1,
                      const float* __restrict__ b1,
                      const float* __restrict__ W2,
                      const float* __restrict__ b2, int n) {
    __shared__ float sh[8192];               // phase A: As+Ws2; phase B: Hs 128x64
    __shared__ float W2s[HIDDEN * CLASSES];  // 8 KB
    __shared__ float b2s[CLASSES];

    int tid = threadIdx.x;
    int tx  = tid & 15;            // hid group (4 hid)
    int ty  = tid >> 4;            // node group (8 nodes)
    int bn  = blockIdx.x * 128;

    for (int i = tid; i < HIDDEN * CLASSES; i += 256) W2s[i] = W2[i];
    if (tid < CLASSES) b2s[tid] = b2[tid];

    // tile loaders
    int anode = tid >> 2;          // 0..63 (+64 for second)
    int ak    = (tid & 3) * 4;     // k 0,4,8,12
    int wk    = tid >> 4;          // 0..15
    int wc    = (tid & 15) * 4;    // hid 0..60
    int wgrp  = wc >> 2;
    int woff  = wgrp * 8 + (wgrp >> 2) * 4;   // dup-skew
    int bo    = tx * 8 + (tx >> 2) * 4;

    int pn0 = bn + anode, pn1 = bn + anode + 64;
    const float* xp0 = (pn0 < n) ? &x[(size_t)pn0 * FEATS + ak] : nullptr;
    const float* xp1 = (pn1 < n) ? &x[(size_t)pn1 * FEATS + ak] : nullptr;
    const float* wp  = &W1[(size_t)wk * HIDDEN + wc];

    unsigned long long acc[4][4];  // [hid j][node-pair p]
    #pragma unroll
    for (int j = 0; j < 4; j++)
        #pragma unroll
        for (int p = 0; p < 4; p++) acc[j][p] = 0ULL;

    // prologue: load tile 0
    float4 pa0 = xp0 ? *(const float4*)xp0 : make_float4(0.f, 0.f, 0.f, 0.f);
    float4 pa1 = xp1 ? *(const float4*)xp1 : make_float4(0.f, 0.f, 0.f, 0.f);
    float4 pw  = *(const float4*)wp;

    for (int k0 = 0; k0 < FEATS; k0 += 16) {
        // stage current tile from prefetch registers
        sh[(ak + 0) * AS_STRIDE + anode] = pa0.x;
        sh[(ak + 1) * AS_STRIDE + anode] = pa0.y;
        sh[(ak + 2) * AS_STRIDE + anode] = pa0.z;
        sh[(ak + 3) * AS_STRIDE + anode] = pa0.w;
        sh[(ak + 0) * AS_STRIDE + anode + 64] = pa1.x;
        sh[(ak + 1) * AS_STRIDE + anode + 64] = pa1.y;
        sh[(ak + 2) * AS_STRIDE + anode + 64] = pa1.z;
        sh[(ak + 3) * AS_STRIDE + anode + 64] = pa1.w;
        *(float4*)&sh[WS_OFF + wk * WS_STRIDE + woff] =
            make_float4(pw.x, pw.x, pw.y, pw.y);
        *(float4*)&sh[WS_OFF + wk * WS_STRIDE + woff + 4] =
            make_float4(pw.z, pw.z, pw.w, pw.w);
        __syncthreads();

        // issue next tile's global loads NOW (overlap with compute below)
        if (k0 + 16 < FEATS) {
            if (xp0) pa0 = *(const float4*)(xp0 + k0 + 16);
            if (xp1) pa1 = *(const float4*)(xp1 + k0 + 16);
            pw = *(const float4*)(wp + (size_t)(k0 + 16) * HIDDEN);
        }

        #pragma unroll
        for (int k = 0; k < 16; k++) {
            ulonglong2 apA = *(const ulonglong2*)&sh[k * AS_STRIDE + ty * 8];
            ulonglong2 apB = *(const ulonglong2*)&sh[k * AS_STRIDE + ty * 8 + 4];
            ulonglong2 w01 = *(const ulonglong2*)&sh[WS_OFF + k * WS_STRIDE + bo];
            ulonglong2 w23 = *(const ulonglong2*)&sh[WS_OFF + k * WS_STRIDE + bo + 4];
            unsigned long long ws[4] = {w01.x, w01.y, w23.x, w23.y};
            #pragma unroll
            for (int j = 0; j < 4; j++) {
                ffma2(acc[j][0], apA.x, ws[j]);
                ffma2(acc[j][1], apA.y, ws[j]);
                ffma2(acc[j][2], apB.x, ws[j]);
                ffma2(acc[j][3], apB.y, ws[j]);
            }
        }
        __syncthreads();
    }

    // epilogue: bias+relu -> Hs[node][hid] (float4 stores)
    float4 bb = *(const float4*)&b1[tx * 4];
    #pragma unroll
    for (int i = 0; i < 8; i++) {
        int p = i >> 1;
        float2 q0 = unpack2(acc[0][p]);
        float2 q1 = unpack2(acc[1][p]);
        float2 q2 = unpack2(acc[2][p]);
        float2 q3 = unpack2(acc[3][p]);
        float4 hv;
        if (i & 1) hv = make_float4(q0.y, q1.y, q2.y, q3.y);
        else       hv = make_float4(q0.x, q1.x, q2.x, q3.x);
        hv.x = fmaxf(hv.x + bb.x, 0.f);
        hv.y = fmaxf(hv.y + bb.y, 0.f);
        hv.z = fmaxf(hv.z + bb.z, 0.f);
        hv.w = fmaxf(hv.w + bb.w, 0.f);
        *(float4*)&sh[(ty * 8 + i) * 64 + tx * 4] = hv;
    }
    __syncthreads();

    // W2 phase: warp w handles 16 nodes; lane = class
    int lane = tid & 31;
    int w    = tid >> 5;
    __half* h0h = (__half*)g_h0uh;
    __half* uA  = (__half*)g_uhA;
    #pragma unroll 1
    for (int t = 0; t < 16; t++) {
        int ln = w * 16 + t;
        int node = bn + ln;
        if (node < n) {
            float s = 0.f;
            #pragma unroll
            for (int k4 = 0; k4 < 16; k4++) {
                float4 hv = *(const float4*)&sh[ln * 64 + k4 * 4];
                s = fmaf(hv.x, W2s[(k4 * 4 + 0) * CLASSES + lane], s);
                s = fmaf(hv.y, W2s[(k4 * 4 + 1) * CLASSES + lane], s);
                s = fmaf(hv.z, W2s[(k4 * 4 + 2) * CLASSES + lane], s);
                s = fmaf(hv.w, W2s[(k4 * 4 + 3) * CLASSES + lane], s);
            }
            s += b2s[lane];
            float rv = g_rinv[node];
            h0h[(size_t)node * CLASSES + lane] = __float2half_rn(0.1f * rv * s);
            uA[(size_t)node * CLASSES + lane]  = __float2half_rn(rv * s);
        }
    }
}

// ---------------- propagation (u-space, fp16 rows, fp32 accumulate) ---------
__global__ void prop_kernel(int parity, float* __restrict__ ext_out, int n) {
    int gw = (blockIdx.x * blockDim.x + threadIdx.x) >> 5;
    if (gw >= n) return;
    int lane = threadIdx.x & 31;
    int grp  = lane >> 2;
    int c    = lane & 3;

    const uint4* u_in = parity ? g_uhB : g_uhA;
    int beg = gw ? __ldg(&g_rowptr[gw - 1]) : 0;
    int end = __ldg(&g_rowptr[gw]);

    float4 lo0 = make_float4(0.f, 0.f, 0.f, 0.f), hi0 = lo0;
    float4 lo1 = lo0, hi1 = lo0;
    int i = beg + grp;
    for (; i + 8 < end; i += 16) {
        int s0 = __ldg(&g_csrs[i]);
        int s1 = __ldg(&g_csrs[i + 8]);
        uint4 v0 = __ldg(&u_in[(size_t)s0 * 4 + c]);
        uint4 v1 = __ldg(&u_in[(size_t)s1 * 4 + c]);
        acc8(lo0, hi0, v0);
        acc8(lo1, hi1, v1);
    }
    if (i < end) {
        int s0 = __ldg(&g_csrs[i]);
        uint4 v0 = __ldg(&u_in[(size_t)s0 * 4 + c]);
        acc8(lo0, hi0, v0);
    }
    lo0.x += lo1.x; lo0.y += lo1.y; lo0.z += lo1.z; lo0.w += lo1.w;
    hi0.x += hi1.x; hi0.y += hi1.y; hi0.z += hi1.z; hi0.w += hi1.w;

    #pragma unroll
    for (int off = 4; off <= 16; off <<= 1) {
        lo0.x += __shfl_xor_sync(0xffffffffu, lo0.x, off);
        lo0.y += __shfl_xor_sync(0xffffffffu, lo0.y, off);
        lo0.z += __shfl_xor_sync(0xffffffffu, lo0.z, off);
        lo0.w += __shfl_xor_sync(0xffffffffu, lo0.w, off);
        hi0.x += __shfl_xor_sync(0xffffffffu, hi0.x, off);
        hi0.y += __shfl_xor_sync(0xffffffffu, hi0.y, off);
        hi0.z += __shfl_xor_sync(0xffffffffu, hi0.z, off);
        hi0.w += __shfl_xor_sync(0xffffffffu, hi0.w, off);
    }
    if (grp == 0) {
        float2 cf = __ldg(&g_coef[gw]);
        uint4 zv = __ldg(&g_h0uh[(size_t)gw * 4 + c]);
        float4 z0, z1;
        cvt8(z0, z1, zv);
        float4 o0, o1;
        o0.x = fmaf(cf.x, lo0.x, z0.x);
        o0.y = fmaf(cf.x, lo0.y, z0.y);
        o0.z = fmaf(cf.x, lo0.z, z0.z);
        o0.w = fmaf(cf.x, lo0.w, z0.w);
        o1.x = fmaf(cf.x, hi0.x, z1.x);
        o1.y = fmaf(cf.x, hi0.y, z1.y);
        o1.z = fmaf(cf.x, hi0.z, z1.z);
        o1.w = fmaf(cf.x, hi0.w, z1.w);
        if (ext_out) {  // final iteration: back to h-space, fp32 out
            o0.x *= cf.y; o0.y *= cf.y; o0.z *= cf.y; o0.w *= cf.y;
            o1.x *= cf.y; o1.y *= cf.y; o1.z *= cf.y; o1.w *= cf.y;
            ((float4*)ext_out)[(size_t)gw * 8 + c * 2]     = o0;
            ((float4*)ext_out)[(size_t)gw * 8 + c * 2 + 1] = o1;
        } else {
            uint4* u_out = parity ? g_uhA : g_uhB;
            u_out[(size_t)gw * 4 + c] = pack8(o0, o1);
        }
    }
}

// ---------------- host driver -----------------------------------------------
extern "C" void kernel_launch(void* const* d_in, const int* in_sizes, int n_in,
                              void* d_out, int out_size) {
    const float* x     = (const float*)d_in[0];
    const int*   edges = (const int*)d_in[1];     // int32 (JAX x64 off)
    const float* W1    = (const float*)d_in[2];
    const float* b1    = (const float*)d_in[3];
    const float* W2    = (const float*)d_in[4];
    const float* b2    = (const float*)d_in[5];

    int n = in_sizes[0] / FEATS;
    int E = in_sizes[1] / 2;

    const int TB = 256;
    int nchunks = (n + SCAN_CHUNK - 1) / SCAN_CHUNK;
    int E4 = (E >> 2) ? (E >> 2) : 1;
    zero_kernel<<<(n + TB - 1) / TB, TB>>>(n);
    deg_kernel<<<(E4 + TB - 1) / TB, TB>>>(edges, E);
    scan_block_kernel<<<nchunks, SCAN_CHUNK>>>(n);
    scan_sums_kernel<<<1, 32>>>(nchunks, n);
    scan_add_kernel<<<(n + SCAN_CHUNK - 1) / SCAN_CHUNK, SCAN_CHUNK>>>(n);
    fill_kernel<<<(E4 + TB - 1) / TB, TB>>>(edges, E);

    mlp_fused_kernel<<<(n + 127) / 128, 256>>>(x, W1, b1, W2, b2, n);

    int prop_blocks = (n * 32 + TB - 1) / TB;   // one warp per node
    for (int it = 0; it < 10; it++) {
        prop_kernel<<<prop_blocks, TB>>>(it & 1,
                                         (it == 9) ? (float*)d_out : nullptr,
                                         n);
    }
}